// round 9
// baseline (speedup 1.0000x reference)
#include <cuda_runtime.h>
#include <cstdint>

#define TT 2048
#define BB 512
#define KK 8
#define DD 32
#define DT_F 0.05f
#define SQDT_F 0.22360679774997896f  /* sqrt(0.05) */
#define UN 2                          /* prefetch group / unroll */

// Scratch (static __device__, no allocs):
// g_wdt: per (t,b) 12 packed floats: [w0*dt,w1*dt,w2*dt,0][w3..w5,0][w6,w7,0,0]
// g_add: addend[t,b,i] = dt*sum_k wn_k b_k[i] + sqrt(dt)*noise[t,b,i]*sum_k wn_k Q_k[i]
__device__ float g_wdt[(size_t)TT * BB * 12];
__device__ float g_add[(size_t)TT * BB * DD];

// ---------- f32x2 helpers (FFMA2 is PTX-only on sm_103a) ----------
__device__ __forceinline__ unsigned long long add2(unsigned long long a, unsigned long long b) {
    unsigned long long d;
    asm("add.rn.f32x2 %0, %1, %2;" : "=l"(d) : "l"(a), "l"(b));
    return d;
}
__device__ __forceinline__ void ffma2(unsigned long long& d, unsigned long long a, unsigned long long b) {
    asm("fma.rn.f32x2 %0, %1, %2, %3;" : "=l"(d) : "l"(a), "l"(b), "l"(d));
}
__device__ __forceinline__ float hsum2(unsigned long long v) {
    float lo, hi;
    asm("mov.b64 {%0, %1}, %2;" : "=f"(lo), "=f"(hi) : "l"(v));
    return lo + hi;
}

// ---------- Kernel 1: fold noise, Q, b, dt into addend + packed dt-weights ----------
// One warp per (t,b) pair; 4 pairs per 128-thread block.
__global__ void __launch_bounds__(128) prep_kernel(
    const float* __restrict__ s_probs,
    const float* __restrict__ noise,
    const float* __restrict__ b_s,
    const float* __restrict__ Q_chol)
{
    __shared__ float sb[KK * DD];
    __shared__ float sq[KK * DD];
    const int tid = threadIdx.x;
    for (int i = tid; i < KK * DD; i += 128) { sb[i] = b_s[i]; sq[i] = Q_chol[i]; }
    __syncthreads();

    const int wid  = tid >> 5;
    const int lane = tid & 31;
    const size_t pair = (size_t)blockIdx.x * 4 + wid;   // = t*BB + b

    const float4* sp = (const float4*)(s_probs + pair * KK);
    float4 a  = sp[0];
    float4 b4 = sp[1];
    float s = ((a.x + a.y) + (a.z + a.w)) + ((b4.x + b4.y) + (b4.z + b4.w));
    float r = 1.0f / s;
    float wn[KK] = { a.x * r, a.y * r, a.z * r, a.w * r,
                     b4.x * r, b4.y * r, b4.z * r, b4.w * r };

    float bb = 0.0f, qq = 0.0f;
#pragma unroll
    for (int k = 0; k < KK; k++) {
        bb = fmaf(wn[k], sb[k * DD + lane], bb);
        qq = fmaf(wn[k], sq[k * DD + lane], qq);
    }
    float nz = noise[pair * DD + lane];
    g_add[pair * DD + lane] = fmaf(DT_F, bb, (SQDT_F * nz) * qq);

    if (lane == 0) {
        float4* o = (float4*)(g_wdt + pair * 12);
        o[0] = make_float4(DT_F * wn[0], DT_F * wn[1], DT_F * wn[2], 0.0f);
        o[1] = make_float4(DT_F * wn[3], DT_F * wn[4], DT_F * wn[5], 0.0f);
        o[2] = make_float4(DT_F * wn[6], DT_F * wn[7], 0.0f, 0.0f);
    }
}

// ---------- Kernel 2: one CTA (96 thr = 3 warps) per batch ----------
// Warp q handles k = {3q, 3q+1, 3q+2}; warp 2's third slot is a dummy
// (duplicate A row, weight exactly 0). All warps run identical code: 8 LDS.128
// + 48 FFMA2 + 1 STS.32 + 1 barrier + 3 LDS.32 per step. Warps land on SMSPs
// 0/1/2 of each SM; 4 CTAs/SM -> ~3.5 warps per used SMSP.
__global__ void __launch_bounds__(96, 4) sde_main(
    const float* __restrict__ z0,
    const float* __restrict__ A_s,
    float* __restrict__ ys)
{
    const int b    = blockIdx.x;
    const int tid  = threadIdx.x;
    const int q    = tid >> 5;       // warp 0..2
    const int lane = tid & 31;       // row i

    __shared__ __align__(16) float zbuf[2][3][DD];   // [parity][warp][row] private z
    __shared__ __align__(16) float pbuf[2][3][DD];   // [parity][warp][row] partial pd

    // ---- A rows -> registers: rows `lane` of A_{3q+kk}, kk=0..2 (dup for dummy) ----
    unsigned long long A[3][16];
#pragma unroll
    for (int kk = 0; kk < 3; kk++) {
        int k = 3 * q + kk;
        if (k > 7) k = 7;            // dummy slot: valid memory, weight is 0
        const ulonglong2* r = (const ulonglong2*)(A_s + (size_t)(k * DD + lane) * DD);
#pragma unroll
        for (int p = 0; p < 8; p++) {
            ulonglong2 v = r[p];
            A[kk][2 * p]     = v.x;
            A[kk][2 * p + 1] = v.y;
        }
    }

    // ---- z init ----
    float zreg = z0[(size_t)b * DD + lane];
    zbuf[0][q][lane] = zreg;

    // stream pointers
    const float4* wp = (const float4*)(g_wdt) + q;    // + (t*BB+b)*3
    const float*  ap = g_add + (size_t)b * DD + lane; // + t*BB*DD
    float*        yp = ys    + (size_t)b * DD + lane;

    // ---- prefetch group 0 ----
    float4 wv_c[UN]; float ad_c[UN];
#pragma unroll
    for (int u = 0; u < UN; u++) {
        wv_c[u] = __ldg(&wp[((size_t)u * BB + b) * 3]);
        ad_c[u] = __ldg(&ap[(size_t)u * (BB * DD)]);
    }

    __syncthreads();

    for (int s0 = 0; s0 < TT; s0 += UN) {
        // ---- prefetch next group (clamped; last-group values unused) ----
        float4 wv_n[UN]; float ad_n[UN];
#pragma unroll
        for (int u = 0; u < UN; u++) {
            int ts = s0 + UN + u;
            if (ts >= TT) ts = TT - 1;
            wv_n[u] = __ldg(&wp[((size_t)ts * BB + b) * 3]);
            ad_n[u] = __ldg(&ap[(size_t)ts * (BB * DD)]);
        }

#pragma unroll
        for (int u = 0; u < UN; u++) {
            const int step = s0 + u;
            const int par  = step & 1;

            // ---- matvec: 3 rows vs z (8 LDS.128 broadcast + 48 FFMA2, 6 chains) ----
            unsigned long long ca[3] = {0ull, 0ull, 0ull};
            unsigned long long cb[3] = {0ull, 0ull, 0ull};
            const ulonglong2* zv = (const ulonglong2*)(&zbuf[par][q][0]);
#pragma unroll
            for (int jj = 0; jj < 8; jj++) {
                ulonglong2 z2 = zv[jj];
#pragma unroll
                for (int kk = 0; kk < 3; kk++) {
                    ffma2(ca[kk], A[kk][2 * jj],     z2.x);
                    ffma2(cb[kk], A[kk][2 * jj + 1], z2.y);
                }
            }
            float a0 = hsum2(add2(ca[0], cb[0]));
            float a1 = hsum2(add2(ca[1], cb[1]));
            float a2 = hsum2(add2(ca[2], cb[2]));

            // ---- weighted partial (weights pre-scaled by dt; dummy weight = 0) ----
            float4 wv = wv_c[u];
            float pd = fmaf(wv.x, a0, fmaf(wv.y, a1, wv.z * a2));

            // ---- cross-warp k-reduction: STS.32 + 1 barrier + 3 LDS.32 ----
            pbuf[par][q][lane] = pd;
            __syncthreads();
            float sum = (pbuf[par][0][lane] + pbuf[par][1][lane]) + pbuf[par][2][lane];

            // ---- z update (all warps redundantly; each publishes own copy) ----
            zreg = zreg + sum + ad_c[u];
            zbuf[par ^ 1][q][lane] = zreg;
            if (q == 2) yp[(size_t)step * (BB * DD)] = zreg;  // coalesced 128B
        }

        // rotate prefetch buffers
#pragma unroll
        for (int u = 0; u < UN; u++) {
            wv_c[u] = wv_n[u];
            ad_c[u] = ad_n[u];
        }
    }
}

extern "C" void kernel_launch(void* const* d_in, const int* in_sizes, int n_in,
                              void* d_out, int out_size) {
    const float* z0      = (const float*)d_in[0];
    const float* s_probs = (const float*)d_in[1];
    const float* noise   = (const float*)d_in[2];
    const float* A_s     = (const float*)d_in[3];
    const float* b_s     = (const float*)d_in[4];
    const float* Q_chol  = (const float*)d_in[5];
    float*       ys      = (float*)d_out;

    prep_kernel<<<(TT * BB) / 4, 128>>>(s_probs, noise, b_s, Q_chol);
    sde_main<<<BB, 96>>>(z0, A_s, ys);
}

// round 10
// speedup vs baseline: 1.2249x; 1.2249x over previous
#include <cuda_runtime.h>
#include <cstdint>

#define TT 2048
#define BB 512
#define KK 8
#define DD 32
#define DT_F 0.05f
#define SQDT_F 0.22360679774997896f  /* sqrt(0.05) */
#define UN 2                          /* prefetch group / unroll */

// Normalized weights packed as (w0,w4)(w1,w5)(w2,w6)(w3,w7) per (t,b):
// lane with k-quarter kq reads float2 at index (t*BB+b)*4 + kq.
__device__ float g_wn[(size_t)TT * BB * KK];

// ---------- f32x2 helpers (FFMA2 is PTX-only on sm_103a) ----------
__device__ __forceinline__ unsigned long long add2(unsigned long long a, unsigned long long b) {
    unsigned long long d;
    asm("add.rn.f32x2 %0, %1, %2;" : "=l"(d) : "l"(a), "l"(b));
    return d;
}
__device__ __forceinline__ void ffma2(unsigned long long& d, unsigned long long a, unsigned long long b) {
    asm("fma.rn.f32x2 %0, %1, %2, %3;" : "=l"(d) : "l"(a), "l"(b), "l"(d));
}
__device__ __forceinline__ float hsum2(unsigned long long v) {
    float lo, hi;
    asm("mov.b64 {%0, %1}, %2;" : "=f"(lo), "=f"(hi) : "l"(v));
    return lo + hi;
}

// ---------- Kernel 1: normalize weights, (k, k+4)-interleaved packing ----------
__global__ void __launch_bounds__(256) norm_kernel(const float* __restrict__ s_probs) {
    int idx = blockIdx.x * blockDim.x + threadIdx.x;  // (t,b) pair
    if (idx < TT * BB) {
        const float4* p = (const float4*)(s_probs + (size_t)idx * KK);
        float4 a = p[0];   // s0..s3
        float4 b = p[1];   // s4..s7
        float s = ((a.x + a.y) + (a.z + a.w)) + ((b.x + b.y) + (b.z + b.w));
        float r = 1.0f / s;
        float4* o = (float4*)(g_wn + (size_t)idx * KK);
        // pairs: (w0,w4) (w1,w5) | (w2,w6) (w3,w7)
        o[0] = make_float4(a.x * r, b.x * r, a.y * r, b.y * r);
        o[1] = make_float4(a.z * r, b.z * r, a.w * r, b.w * r);
    }
}

// ---------- Kernel 2: one CTA (128 thr = 4 warps) per batch, ROW-split ----------
// Warp w owns rows 8w..8w+7 for ALL 8 k. Lane l: row = 8w + (l>>2),
// kq = l&3 -> k in {kq, kq+4} (64 A-floats = 32 ull regs). The k-reduction is
// 2 intra-warp butterflies over the 4 kq-lanes of each row; bias/diffusion
// terms ride inside the same reduction. Only barrier: z broadcast (1/step).
// ~105 regs -> 4 CTAs/SM -> 4 warps on EVERY SMSP.
__global__ void __launch_bounds__(128, 4) sde_main(
    const float* __restrict__ z0,
    const float* __restrict__ noise,
    const float* __restrict__ A_s,
    const float* __restrict__ b_s,
    const float* __restrict__ Q_chol,
    float* __restrict__ ys)
{
    const int b    = blockIdx.x;
    const int tid  = threadIdx.x;
    const int w    = tid >> 5;
    const int l    = tid & 31;
    const int kq   = l & 3;
    const int row  = 8 * w + (l >> 2);
    const int k0   = kq;
    const int k1   = kq + 4;

    __shared__ __align__(16) float zbuf[2][DD];   // [parity][row], shared by all warps

    // ---- A rows -> registers as f32x2 pairs (row `row` of A_k0 and A_k1) ----
    unsigned long long Aa[16], Ab[16];
    {
        const ulonglong2* r0 = (const ulonglong2*)(A_s + (size_t)(k0 * DD + row) * DD);
        const ulonglong2* r1 = (const ulonglong2*)(A_s + (size_t)(k1 * DD + row) * DD);
#pragma unroll
        for (int p = 0; p < 8; p++) {
            ulonglong2 v0 = r0[p]; Aa[2 * p] = v0.x; Aa[2 * p + 1] = v0.y;
            ulonglong2 v1 = r1[p]; Ab[2 * p] = v1.x; Ab[2 * p + 1] = v1.y;
        }
    }
    const float dtb0 = DT_F * b_s[k0 * DD + row];
    const float dtb1 = DT_F * b_s[k1 * DD + row];
    const float qc0  = Q_chol[k0 * DD + row];
    const float qc1  = Q_chol[k1 * DD + row];

    // ---- z init (each lane keeps its row's z in a register) ----
    float zreg = z0[(size_t)b * DD + row];
    if (tid < DD) zbuf[0][tid] = z0[(size_t)b * DD + tid];

    // stream pointers
    const float2* wp2 = (const float2*)g_wn;            // + (t*BB+b)*4 + kq
    const float*  np  = noise + (size_t)b * DD + row;   // + t*BB*DD
    float*        yp  = ys    + (size_t)b * DD + row;

    // ---- prefetch group 0 ----
    float2 wv_c[UN]; float dw_c[UN];
#pragma unroll
    for (int u = 0; u < UN; u++) {
        wv_c[u] = __ldg(&wp2[((size_t)u * BB + b) * 4 + kq]);
        dw_c[u] = SQDT_F * __ldg(&np[(size_t)u * (BB * DD)]);
    }

    __syncthreads();

    for (int s0 = 0; s0 < TT; s0 += UN) {
        // ---- prefetch next group (clamped; last-group values unused) ----
        float2 wv_n[UN]; float dw_n[UN];
#pragma unroll
        for (int u = 0; u < UN; u++) {
            int ts = s0 + UN + u;
            if (ts >= TT) ts = TT - 1;
            wv_n[u] = __ldg(&wp2[((size_t)ts * BB + b) * 4 + kq]);
            dw_n[u] = SQDT_F * __ldg(&np[(size_t)ts * (BB * DD)]);
        }

#pragma unroll
        for (int u = 0; u < UN; u++) {
            const int step = s0 + u;
            const int par  = step & 1;

            // ---- matvec: row of A_k0, A_k1 vs z (8 LDS.128 + 32 FFMA2) ----
            unsigned long long c0a = 0ull, c0b = 0ull, c1a = 0ull, c1b = 0ull;
            const ulonglong2* zv = (const ulonglong2*)(&zbuf[par][0]);
#pragma unroll
            for (int jj = 0; jj < 8; jj++) {
                ulonglong2 z2 = zv[jj];                 // LDS.128 broadcast
                ffma2(c0a, Aa[2 * jj],     z2.x);
                ffma2(c0b, Aa[2 * jj + 1], z2.y);
                ffma2(c1a, Ab[2 * jj],     z2.x);
                ffma2(c1b, Ab[2 * jj + 1], z2.y);
            }
            float a0 = hsum2(add2(c0a, c0b));
            float a1 = hsum2(add2(c1a, c1b));

            // ---- full per-k term incl. bias + diffusion, weighted combine ----
            float2 wv  = wv_c[u];
            float  dwi = dw_c[u];
            float t0 = fmaf(qc0, dwi, fmaf(DT_F, a0, dtb0));
            float t1 = fmaf(qc1, dwi, fmaf(DT_F, a1, dtb1));
            float pd = fmaf(wv.x, t0, wv.y * t1);

            // ---- k-reduction: 2 butterflies over the 4 kq-lanes of this row ----
            pd += __shfl_xor_sync(0xFFFFFFFFu, pd, 1);
            pd += __shfl_xor_sync(0xFFFFFFFFu, pd, 2);

            // ---- z update (4 lanes redundant; kq==0 publishes) ----
            zreg += pd;
            if (kq == 0) {
                zbuf[par ^ 1][row] = zreg;              // 8 lanes/warp, 32B span
                yp[(size_t)step * (BB * DD)] = zreg;    // CTA covers one 128B line
            }
            __syncthreads();
        }

        // rotate prefetch buffers
#pragma unroll
        for (int u = 0; u < UN; u++) {
            wv_c[u] = wv_n[u];
            dw_c[u] = dw_n[u];
        }
    }
}

extern "C" void kernel_launch(void* const* d_in, const int* in_sizes, int n_in,
                              void* d_out, int out_size) {
    const float* z0      = (const float*)d_in[0];
    const float* s_probs = (const float*)d_in[1];
    const float* noise   = (const float*)d_in[2];
    const float* A_s     = (const float*)d_in[3];
    const float* b_s     = (const float*)d_in[4];
    const float* Q_chol  = (const float*)d_in[5];
    float*       ys      = (float*)d_out;

    norm_kernel<<<(TT * BB + 255) / 256, 256>>>(s_probs);
    sde_main<<<BB, 128>>>(z0, noise, A_s, b_s, Q_chol, ys);
}